// round 9
// baseline (speedup 1.0000x reference)
#include <cuda_runtime.h>
#include <cuda_bf16.h>

// ZBL screened nuclear repulsion:
//   expv = Dij/d * (Zi^p + Zj^p)
//   vij  = sum_k c[k] * exp(-a[k]*expv)
//   out  = segment_sum(vij, idx_i)   (idx_i sorted)
//
// R9: R8's slim prefetch pipeline on a PERSISTENT balanced grid.
// 148 SMs x 6 CTAs (the 40-reg residency limit) in ONE wave; each thread
// grid-strides ~17 iterations. Removes the 4.4-wave quantization + spread
// that held R8's achieved occupancy at 66% vs 75% theoretical, and lets
// per-iteration j-gather latency jitter average out over many iterations.

#define TPB        256
#define SM_COUNT   148
#define CTAS_PER_SM 6

__device__ __forceinline__ float ex2(float x) {
    float y;
    asm("ex2.approx.f32 %0, %1;" : "=f"(y) : "f"(x));
    return y;
}
__device__ __forceinline__ float lg2(float x) {
    float y;
    asm("lg2.approx.f32 %0, %1;" : "=f"(y) : "f"(x));
    return y;
}

// ---------------------------------------------------------------------------
__global__ __launch_bounds__(TPB)
void zbl_main_kernel(const float4* __restrict__ Dij4,
                     const int4*   __restrict__ idx_i4,
                     const int4*   __restrict__ idx_j4,
                     const int*    __restrict__ Z,
                     const float*  __restrict__ p_ptr,
                     const float*  __restrict__ d_ptr,
                     const float*  __restrict__ c_ptr,
                     const float*  __restrict__ a_ptr,
                     float*        __restrict__ out,
                     int V)   // number of 4-edge vectors
{
    const float p    = __ldg(p_ptr);
    const float invd = 1.0f / __ldg(d_ptr);
    const float c0 = __ldg(c_ptr + 0), c1 = __ldg(c_ptr + 1);
    const float c2 = __ldg(c_ptr + 2), c3 = __ldg(c_ptr + 3);
    // b_k = -a_k * log2(e) / d : folds exp->ex2 base change and 1/d
    const float NL2E = -1.4426950408889634f * invd;
    const float b0 = __ldg(a_ptr + 0) * NL2E, b1 = __ldg(a_ptr + 1) * NL2E;
    const float b2 = __ldg(a_ptr + 2) * NL2E, b3 = __ldg(a_ptr + 3) * NL2E;

    const int stride = gridDim.x * blockDim.x;
    int v = blockIdx.x * blockDim.x + threadIdx.x;

    const unsigned m = 0xFFFFFFFFu;
    const int lane = threadIdx.x & 31;

    // ---- prologue: prefetch iteration 0's index vectors (gather roots) ----
    bool valid = (v < V);
    int4 ii = make_int4(0, 0, 0, 0);
    int4 jj = make_int4(0, 0, 0, 0);
    if (valid) {
        ii = __ldg(idx_i4 + v);
        jj = __ldg(idx_j4 + v);
    }

    // Dynamic grid-stride loop. Lanes of a warp differ in `valid` only on the
    // final partial iteration; __any_sync keeps the warp converged so the
    // full-mask shuffles below stay legal.
    while (__any_sync(m, valid)) {
        int   cur = -1;     // pending segment id (tail)
        float acc = 0.0f;   // pending segment sum

        // ---- next iteration's index prefetch (overlaps this iter's chain) ----
        const int  vn     = v + stride;
        const bool nvalid = (vn < V);
        int4 ii_n = make_int4(0, 0, 0, 0);
        int4 jj_n = make_int4(0, 0, 0, 0);
        if (nvalid) {
            ii_n = __ldg(idx_i4 + vn);
            jj_n = __ldg(idx_j4 + vn);
        }

        if (valid) {
            // ---- Dij load: independent of the gather chain, self-hiding ----
            const float4 dd = __ldg(Dij4 + v);

            // ---- 8 independent scalar gathers from the input Z array ----
            const int zi0 = __ldg(Z + ii.x), zi1 = __ldg(Z + ii.y);
            const int zi2 = __ldg(Z + ii.z), zi3 = __ldg(Z + ii.w);
            const int zj0 = __ldg(Z + jj.x), zj1 = __ldg(Z + jj.y);
            const int zj2 = __ldg(Z + jj.z), zj3 = __ldg(Z + jj.w);

            // ---- z^p via MUFU: ex2(p*lg2 z); z=0 -> -inf -> 0 = pow(0,p) ----
            const float fi0 = ex2(p * lg2((float)zi0));
            const float fi1 = ex2(p * lg2((float)zi1));
            const float fi2 = ex2(p * lg2((float)zi2));
            const float fi3 = ex2(p * lg2((float)zi3));
            const float fj0 = ex2(p * lg2((float)zj0));
            const float fj1 = ex2(p * lg2((float)zj1));
            const float fj2 = ex2(p * lg2((float)zj2));
            const float fj3 = ex2(p * lg2((float)zj3));

            const float e0 = dd.x * (fi0 + fj0);
            const float e1 = dd.y * (fi1 + fj1);
            const float e2 = dd.z * (fi2 + fj2);
            const float e3 = dd.w * (fi3 + fj3);

            const float v0 = c0*ex2(b0*e0) + c1*ex2(b1*e0) + c2*ex2(b2*e0) + c3*ex2(b3*e0);
            const float v1 = c0*ex2(b0*e1) + c1*ex2(b1*e1) + c2*ex2(b2*e1) + c3*ex2(b3*e1);
            const float v2 = c0*ex2(b0*e2) + c1*ex2(b1*e2) + c2*ex2(b2*e2) + c3*ex2(b3*e2);
            const float v3 = c0*ex2(b0*e3) + c1*ex2(b1*e3) + c2*ex2(b2*e3) + c3*ex2(b3*e3);

            // ---- sequential merge of the 4 sorted edges; flush interior runs ----
            cur = ii.x; acc = v0;
            if (ii.y == cur) acc += v1; else { atomicAdd(out + cur, acc); cur = ii.y; acc = v1; }
            if (ii.z == cur) acc += v2; else { atomicAdd(out + cur, acc); cur = ii.z; acc = v2; }
            if (ii.w == cur) acc += v3; else { atomicAdd(out + cur, acc); cur = ii.w; acc = v3; }
        }

        // ---- warp-segmented inclusive scan over the pending tails ----
        // Edges sorted by idx_i; equal tail ids are contiguous across lanes.
        // Invalid lanes carry cur=-1 and are excluded by the cur>=0 guard.
        #pragma unroll
        for (int o = 1; o < 32; o <<= 1) {
            const float vv = __shfl_up_sync(m, acc, o);
            const int   ss = __shfl_up_sync(m, cur, o);
            if (lane >= o && ss == cur) acc += vv;
        }
        const int nxt = __shfl_down_sync(m, cur, 1);
        if (cur >= 0 && (lane == 31 || nxt != cur)) {
            atomicAdd(out + cur, acc);
        }

        // ---- rotate pipeline ----
        v = vn; valid = nvalid;
        ii = ii_n; jj = jj_n;
    }
}

// ---------------------------------------------------------------------------
// Tail kernel: handles E % 4 leftover edges (0 for this shape, but correct
// in general).
__global__ void zbl_tail_kernel(const float* __restrict__ Dij,
                                const int*   __restrict__ idx_i,
                                const int*   __restrict__ idx_j,
                                const int*   __restrict__ Z,
                                const float* __restrict__ p_ptr,
                                const float* __restrict__ d_ptr,
                                const float* __restrict__ c_ptr,
                                const float* __restrict__ a_ptr,
                                float*       __restrict__ out,
                                int start, int E)
{
    const float p    = __ldg(p_ptr);
    const float invd = 1.0f / __ldg(d_ptr);
    const float NL2E = -1.4426950408889634f * invd;
    const int e = start + blockIdx.x * blockDim.x + threadIdx.x;
    if (e < E) {
        const int   si = __ldg(idx_i + e);
        const int   sj = __ldg(idx_j + e);
        const float zpi = ex2(p * lg2((float)__ldg(Z + si)));
        const float zpj = ex2(p * lg2((float)__ldg(Z + sj)));
        const float ev  = __ldg(Dij + e) * (zpi + zpj);
        float vsum = 0.0f;
        #pragma unroll
        for (int k = 0; k < 4; k++)
            vsum += __ldg(c_ptr + k) * ex2(__ldg(a_ptr + k) * NL2E * ev);
        atomicAdd(out + si, vsum);
    }
}

// ---------------------------------------------------------------------------
extern "C" void kernel_launch(void* const* d_in, const int* in_sizes, int n_in,
                              void* d_out, int out_size)
{
    const int*   Z     = (const int*)  d_in[0];
    const float* Dij   = (const float*)d_in[1];
    const int*   idx_i = (const int*)  d_in[2];
    const int*   idx_j = (const int*)  d_in[3];
    const float* p_ptr = (const float*)d_in[4];
    const float* d_ptr = (const float*)d_in[5];
    const float* c_ptr = (const float*)d_in[6];
    const float* a_ptr = (const float*)d_in[7];
    float* out = (float*)d_out;

    const int E = in_sizes[1];
    const int V = E / 4;            // full 4-edge vectors
    const int tail_start = V * 4;

    // 1) zero the poisoned output (graph-capturable memset node)
    cudaMemsetAsync(out, 0, (size_t)out_size * sizeof(float));

    // 2) persistent balanced grid: one wave of SM_COUNT*CTAS_PER_SM CTAs,
    //    each thread grid-strides through the vectors.
    {
        int blocks = SM_COUNT * CTAS_PER_SM;
        const int max_blocks = (V + TPB - 1) / TPB;   // never launch idle CTAs
        if (blocks > max_blocks) blocks = max_blocks;
        if (blocks < 1) blocks = 1;
        zbl_main_kernel<<<blocks, TPB>>>(
            reinterpret_cast<const float4*>(Dij),
            reinterpret_cast<const int4*>(idx_i),
            reinterpret_cast<const int4*>(idx_j),
            Z, p_ptr, d_ptr, c_ptr, a_ptr, out, V);
    }

    // 3) leftover edges (E % 4), if any
    if (tail_start < E) {
        const int n = E - tail_start;
        zbl_tail_kernel<<<(n + 63) / 64, 64>>>(Dij, idx_i, idx_j, Z,
                                               p_ptr, d_ptr, c_ptr, a_ptr,
                                               out, tail_start, E);
    }
}

// round 10
// speedup vs baseline: 1.0301x; 1.0301x over previous
#include <cuda_runtime.h>
#include <cuda_bf16.h>

// ZBL screened nuclear repulsion:
//   expv = Dij/d * (Zi^p + Zj^p)
//   vij  = sum_k c[k] * exp(-a[k]*expv)
//   out  = segment_sum(vij, idx_i)   (idx_i sorted)
//
// R10: exact R8 skeleton (best: main 66.0us; fixed-trip ITERS=4, slim idx
// prefetch, MUFU z^p, warp-segmented reduction) + ONE change: the three
// streaming vector loads use __ldcs (evict-first). They touch 192MB exactly
// once and were thrashing the 228KB L1, holding the 2MB Z gather table at
// ~90% miss and pushing ~512MB of j-gather sectors through L2 (which sits
// at the ~12TB/s LTS chip cap — the real binder). Keeping L1 for Z converts
// part of those misses to hits and takes pressure off LTS.

#define EPT   4
#define TPB   256
#define ITERS 4

__device__ __forceinline__ float ex2(float x) {
    float y;
    asm("ex2.approx.f32 %0, %1;" : "=f"(y) : "f"(x));
    return y;
}
__device__ __forceinline__ float lg2(float x) {
    float y;
    asm("lg2.approx.f32 %0, %1;" : "=f"(y) : "f"(x));
    return y;
}

// ---------------------------------------------------------------------------
__global__ __launch_bounds__(TPB)
void zbl_main_kernel(const float4* __restrict__ Dij4,
                     const int4*   __restrict__ idx_i4,
                     const int4*   __restrict__ idx_j4,
                     const int*    __restrict__ Z,
                     const float*  __restrict__ p_ptr,
                     const float*  __restrict__ d_ptr,
                     const float*  __restrict__ c_ptr,
                     const float*  __restrict__ a_ptr,
                     float*        __restrict__ out,
                     int V)   // number of 4-edge vectors
{
    const float p    = __ldg(p_ptr);
    const float invd = 1.0f / __ldg(d_ptr);
    const float c0 = __ldg(c_ptr + 0), c1 = __ldg(c_ptr + 1);
    const float c2 = __ldg(c_ptr + 2), c3 = __ldg(c_ptr + 3);
    // b_k = -a_k * log2(e) / d : folds exp->ex2 base change and 1/d
    const float NL2E = -1.4426950408889634f * invd;
    const float b0 = __ldg(a_ptr + 0) * NL2E, b1 = __ldg(a_ptr + 1) * NL2E;
    const float b2 = __ldg(a_ptr + 2) * NL2E, b3 = __ldg(a_ptr + 3) * NL2E;

    const int stride = gridDim.x * blockDim.x;
    int v = blockIdx.x * blockDim.x + threadIdx.x;

    const unsigned m = 0xFFFFFFFFu;
    const int lane = threadIdx.x & 31;

    // ---- prologue: prefetch iteration 0's index vectors (gather roots).
    // Streaming data is touched once: evict-first keeps L1 for the Z table.
    bool valid = (v < V);
    int4 ii = make_int4(0, 0, 0, 0);
    int4 jj = make_int4(0, 0, 0, 0);
    if (valid) {
        ii = __ldcs(idx_i4 + v);
        jj = __ldcs(idx_j4 + v);
    }

    #pragma unroll 1
    for (int k = 0; k < ITERS; k++) {
        int   cur = -1;     // pending segment id (tail)
        float acc = 0.0f;   // pending segment sum

        // next iteration's index prefetch (issued before this iteration's
        // dependent work so the DRAM hop overlaps the gather+math+scan)
        const int  vn     = v + stride;
        const bool nvalid = (k + 1 < ITERS) && (vn < V);
        int4 ii_n = make_int4(0, 0, 0, 0);
        int4 jj_n = make_int4(0, 0, 0, 0);
        if (nvalid) {
            ii_n = __ldcs(idx_i4 + vn);
            jj_n = __ldcs(idx_j4 + vn);
        }

        if (valid) {
            // ---- Dij load: independent of the gather chain, self-hiding ----
            const float4 dd = __ldcs(Dij4 + v);

            // ---- 8 independent scalar gathers; default caching keeps the
            //      2MB Z table resident in the (now unthrashed) L1 ----
            const int zi0 = __ldg(Z + ii.x), zi1 = __ldg(Z + ii.y);
            const int zi2 = __ldg(Z + ii.z), zi3 = __ldg(Z + ii.w);
            const int zj0 = __ldg(Z + jj.x), zj1 = __ldg(Z + jj.y);
            const int zj2 = __ldg(Z + jj.z), zj3 = __ldg(Z + jj.w);

            // ---- z^p via MUFU: ex2(p*lg2 z); z=0 -> -inf -> 0 = pow(0,p) ----
            const float fi0 = ex2(p * lg2((float)zi0));
            const float fi1 = ex2(p * lg2((float)zi1));
            const float fi2 = ex2(p * lg2((float)zi2));
            const float fi3 = ex2(p * lg2((float)zi3));
            const float fj0 = ex2(p * lg2((float)zj0));
            const float fj1 = ex2(p * lg2((float)zj1));
            const float fj2 = ex2(p * lg2((float)zj2));
            const float fj3 = ex2(p * lg2((float)zj3));

            const float e0 = dd.x * (fi0 + fj0);
            const float e1 = dd.y * (fi1 + fj1);
            const float e2 = dd.z * (fi2 + fj2);
            const float e3 = dd.w * (fi3 + fj3);

            const float v0 = c0*ex2(b0*e0) + c1*ex2(b1*e0) + c2*ex2(b2*e0) + c3*ex2(b3*e0);
            const float v1 = c0*ex2(b0*e1) + c1*ex2(b1*e1) + c2*ex2(b2*e1) + c3*ex2(b3*e1);
            const float v2 = c0*ex2(b0*e2) + c1*ex2(b1*e2) + c2*ex2(b2*e2) + c3*ex2(b3*e2);
            const float v3 = c0*ex2(b0*e3) + c1*ex2(b1*e3) + c2*ex2(b2*e3) + c3*ex2(b3*e3);

            // ---- sequential merge of the 4 sorted edges; flush interior runs ----
            cur = ii.x; acc = v0;
            if (ii.y == cur) acc += v1; else { atomicAdd(out + cur, acc); cur = ii.y; acc = v1; }
            if (ii.z == cur) acc += v2; else { atomicAdd(out + cur, acc); cur = ii.z; acc = v2; }
            if (ii.w == cur) acc += v3; else { atomicAdd(out + cur, acc); cur = ii.w; acc = v3; }
        }

        // ---- warp-segmented inclusive scan over the pending tails ----
        // Edges sorted by idx_i; equal tail ids are contiguous across lanes.
        // Invalid lanes carry cur=-1 and are excluded by the cur>=0 guard.
        #pragma unroll
        for (int o = 1; o < 32; o <<= 1) {
            const float vv = __shfl_up_sync(m, acc, o);
            const int   ss = __shfl_up_sync(m, cur, o);
            if (lane >= o && ss == cur) acc += vv;
        }
        const int nxt = __shfl_down_sync(m, cur, 1);
        if (cur >= 0 && (lane == 31 || nxt != cur)) {
            atomicAdd(out + cur, acc);
        }

        // ---- rotate pipeline ----
        v = vn; valid = nvalid;
        ii = ii_n; jj = jj_n;
    }
}

// ---------------------------------------------------------------------------
// Tail kernel: handles E % 4 leftover edges (0 for this shape, but correct
// in general).
__global__ void zbl_tail_kernel(const float* __restrict__ Dij,
                                const int*   __restrict__ idx_i,
                                const int*   __restrict__ idx_j,
                                const int*   __restrict__ Z,
                                const float* __restrict__ p_ptr,
                                const float* __restrict__ d_ptr,
                                const float* __restrict__ c_ptr,
                                const float* __restrict__ a_ptr,
                                float*       __restrict__ out,
                                int start, int E)
{
    const float p    = __ldg(p_ptr);
    const float invd = 1.0f / __ldg(d_ptr);
    const float NL2E = -1.4426950408889634f * invd;
    const int e = start + blockIdx.x * blockDim.x + threadIdx.x;
    if (e < E) {
        const int   si = __ldg(idx_i + e);
        const int   sj = __ldg(idx_j + e);
        const float zpi = ex2(p * lg2((float)__ldg(Z + si)));
        const float zpj = ex2(p * lg2((float)__ldg(Z + sj)));
        const float ev  = __ldg(Dij + e) * (zpi + zpj);
        float vsum = 0.0f;
        #pragma unroll
        for (int k = 0; k < 4; k++)
            vsum += __ldg(c_ptr + k) * ex2(__ldg(a_ptr + k) * NL2E * ev);
        atomicAdd(out + si, vsum);
    }
}

// ---------------------------------------------------------------------------
extern "C" void kernel_launch(void* const* d_in, const int* in_sizes, int n_in,
                              void* d_out, int out_size)
{
    const int*   Z     = (const int*)  d_in[0];
    const float* Dij   = (const float*)d_in[1];
    const int*   idx_i = (const int*)  d_in[2];
    const int*   idx_j = (const int*)  d_in[3];
    const float* p_ptr = (const float*)d_in[4];
    const float* d_ptr = (const float*)d_in[5];
    const float* c_ptr = (const float*)d_in[6];
    const float* a_ptr = (const float*)d_in[7];
    float* out = (float*)d_out;

    const int E = in_sizes[1];
    const int V = E / 4;            // full 4-edge vectors
    const int tail_start = V * 4;

    // 1) zero the poisoned output (graph-capturable memset node)
    cudaMemsetAsync(out, 0, (size_t)out_size * sizeof(float));

    // 2) pipelined main kernel: each thread handles ITERS vectors grid-stride
    {
        const long long threads_needed = ((long long)V + ITERS - 1) / ITERS;
        const int blocks = (int)((threads_needed + TPB - 1) / TPB);
        zbl_main_kernel<<<blocks, TPB>>>(
            reinterpret_cast<const float4*>(Dij),
            reinterpret_cast<const int4*>(idx_i),
            reinterpret_cast<const int4*>(idx_j),
            Z, p_ptr, d_ptr, c_ptr, a_ptr, out, V);
    }

    // 3) leftover edges (E % 4), if any
    if (tail_start < E) {
        const int n = E - tail_start;
        zbl_tail_kernel<<<(n + 63) / 64, 64>>>(Dij, idx_i, idx_j, Z,
                                               p_ptr, d_ptr, c_ptr, a_ptr,
                                               out, tail_start, E);
    }
}